// round 16
// baseline (speedup 1.0000x reference)
#include <cuda_runtime.h>
#include <math.h>

#define NROWS 500000
#define DIM   256
#define BSEG  16384
#define KC    32
#define MT    32

// ---- scratch (device globals: no cudaMalloc allowed) ----
__device__ float g_localrep[BSEG * DIM];
__device__ float g_T[BSEG * DIM];
__device__ float g_globalrep[BSEG * DIM];
__device__ float g_att[NROWS];
__device__ int   g_segstart[BSEG + 1];

// ---------------------------------------------------------------------------
// K0: segment offsets via binary search (batch is sorted).
// segstart[b] = first index i with batch[i] >= b.
// ---------------------------------------------------------------------------
__global__ void segstart_kernel(const int* __restrict__ batch, int* __restrict__ segstart)
{
    int t = blockIdx.x * blockDim.x + threadIdx.x;
    if (t > BSEG) return;
    int lo = 0, hi = NROWS;
    while (lo < hi) {
        int m = (lo + hi) >> 1;
        if (batch[m] < t) lo = m + 1; else hi = m;
    }
    segstart[t] = lo;
}

// ---------------------------------------------------------------------------
// K1 / K4: per-segment weighted sum: out[b,:] = sum_{i in seg b} w[i] * x[i,:]
// One block (64 threads, float4 per thread) per segment. Coalesced x reads.
// ---------------------------------------------------------------------------
__global__ __launch_bounds__(64) void seg_pool_kernel(
    const float* __restrict__ x, const float* __restrict__ w,
    const int* __restrict__ segstart, float* __restrict__ out)
{
    int b = blockIdx.x;
    int s = segstart[b], e = segstart[b + 1];
    int c = threadIdx.x * 4;

    float4 a0 = make_float4(0.f, 0.f, 0.f, 0.f);
    float4 a1 = make_float4(0.f, 0.f, 0.f, 0.f);

    int i = s;
    for (; i + 1 < e; i += 2) {
        float w0 = w[i], w1 = w[i + 1];
        float4 v0 = *(const float4*)&x[(size_t)i * DIM + c];
        float4 v1 = *(const float4*)&x[(size_t)(i + 1) * DIM + c];
        a0.x = fmaf(w0, v0.x, a0.x); a0.y = fmaf(w0, v0.y, a0.y);
        a0.z = fmaf(w0, v0.z, a0.z); a0.w = fmaf(w0, v0.w, a0.w);
        a1.x = fmaf(w1, v1.x, a1.x); a1.y = fmaf(w1, v1.y, a1.y);
        a1.z = fmaf(w1, v1.z, a1.z); a1.w = fmaf(w1, v1.w, a1.w);
    }
    if (i < e) {
        float w0 = w[i];
        float4 v0 = *(const float4*)&x[(size_t)i * DIM + c];
        a0.x = fmaf(w0, v0.x, a0.x); a0.y = fmaf(w0, v0.y, a0.y);
        a0.z = fmaf(w0, v0.z, a0.z); a0.w = fmaf(w0, v0.w, a0.w);
    }
    a0.x += a1.x; a0.y += a1.y; a0.z += a1.z; a0.w += a1.w;
    *(float4*)&out[(size_t)b * DIM + c] = a0;
}

// ---------------------------------------------------------------------------
// K2 / K5: C[M,256] = A@W + bias0 (+bias1).  K = 256 or 512.
// For K=512, k in [0,256) reads A0, k in [256,512) reads A1 (concat).
// Tile: 32 rows x 256 cols, 256 threads, 8x4 fp32 accumulators/thread.
// ---------------------------------------------------------------------------
__global__ __launch_bounds__(256) void gemm_kernel(
    const float* __restrict__ A0, const float* __restrict__ A1,
    const float* __restrict__ W, int K,
    const float* __restrict__ bias0, const float* __restrict__ bias1,
    float* __restrict__ C)
{
    __shared__ float W_s[KC * DIM];   // 32 KB
    __shared__ float A_s[MT * KC];    // 4 KB

    const int tid = threadIdx.x;
    const int tx  = tid & 63;         // column group (4 cols)
    const int ty  = tid >> 6;         // row group (8 rows)
    const int row0 = blockIdx.x * MT;
    const int c0   = tx * 4;

    float acc[8][4];
#pragma unroll
    for (int r = 0; r < 8; r++)
#pragma unroll
        for (int j = 0; j < 4; j++) acc[r][j] = 0.f;

    for (int kb = 0; kb < K; kb += KC) {
        const float* A = (kb < DIM) ? A0 : A1;
        int acol = kb & (DIM - 1);
        // stage A chunk: 32 rows x 32 k (one float4 per thread)
        {
            int arow = tid >> 3;
            int k4   = (tid & 7) << 2;
            float4 v = *(const float4*)&A[(size_t)(row0 + arow) * DIM + acol + k4];
            *(float4*)&A_s[arow * KC + k4] = v;
        }
        // stage W chunk: 32 k x 256 cols
#pragma unroll
        for (int j = 0; j < 8; j++) {
            int idx  = tid + j * 256;
            int krow = idx >> 6;
            int c4   = (idx & 63) << 2;
            *(float4*)&W_s[krow * DIM + c4] =
                *(const float4*)&W[(size_t)(kb + krow) * DIM + c4];
        }
        __syncthreads();
#pragma unroll 8
        for (int kk = 0; kk < KC; kk++) {
            float4 bv = *(const float4*)&W_s[kk * DIM + c0];
#pragma unroll
            for (int r = 0; r < 8; r++) {
                float a = A_s[(ty * 8 + r) * KC + kk];
                acc[r][0] = fmaf(a, bv.x, acc[r][0]);
                acc[r][1] = fmaf(a, bv.y, acc[r][1]);
                acc[r][2] = fmaf(a, bv.z, acc[r][2]);
                acc[r][3] = fmaf(a, bv.w, acc[r][3]);
            }
        }
        __syncthreads();
    }

    float4 bb = *(const float4*)&bias0[c0];
    if (bias1) {
        float4 b2v = *(const float4*)&bias1[c0];
        bb.x += b2v.x; bb.y += b2v.y; bb.z += b2v.z; bb.w += b2v.w;
    }
#pragma unroll
    for (int r = 0; r < 8; r++) {
        int row = row0 + ty * 8 + r;
        float4 o;
        o.x = acc[r][0] + bb.x; o.y = acc[r][1] + bb.y;
        o.z = acc[r][2] + bb.z; o.w = acc[r][3] + bb.w;
        *(float4*)&C[(size_t)row * DIM + c0] = o;
    }
}

// ---------------------------------------------------------------------------
// K3: att[i] = sigmoid(x[i]@W2 + T[batch[i]]) . w3     (the 32.8 G-FMA kernel)
// Same tiling as gemm_kernel; fused gather + sigmoid + dot-reduce epilogue.
// N = 500000 = 32 * 15625 exactly -> no row guards.
// ---------------------------------------------------------------------------
__global__ __launch_bounds__(256) void att_kernel(
    const float* __restrict__ x, const float* __restrict__ W2,
    const float* __restrict__ T, const int* __restrict__ batch,
    const float* __restrict__ w3, float* __restrict__ att)
{
    __shared__ float W_s[KC * DIM];   // 32 KB (reused for partial sums)
    __shared__ float A_s[MT * KC];    // 4 KB

    const int tid = threadIdx.x;
    const int tx  = tid & 63;
    const int ty  = tid >> 6;
    const int row0 = blockIdx.x * MT;
    const int c0   = tx * 4;

    float acc[8][4];
#pragma unroll
    for (int r = 0; r < 8; r++)
#pragma unroll
        for (int j = 0; j < 4; j++) acc[r][j] = 0.f;

    for (int kb = 0; kb < DIM; kb += KC) {
        {
            int arow = tid >> 3;
            int k4   = (tid & 7) << 2;
            float4 v = *(const float4*)&x[(size_t)(row0 + arow) * DIM + kb + k4];
            *(float4*)&A_s[arow * KC + k4] = v;
        }
#pragma unroll
        for (int j = 0; j < 8; j++) {
            int idx  = tid + j * 256;
            int krow = idx >> 6;
            int c4   = (idx & 63) << 2;
            *(float4*)&W_s[krow * DIM + c4] =
                *(const float4*)&W2[(size_t)(kb + krow) * DIM + c4];
        }
        __syncthreads();
#pragma unroll 8
        for (int kk = 0; kk < KC; kk++) {
            float4 bv = *(const float4*)&W_s[kk * DIM + c0];
#pragma unroll
            for (int r = 0; r < 8; r++) {
                float a = A_s[(ty * 8 + r) * KC + kk];
                acc[r][0] = fmaf(a, bv.x, acc[r][0]);
                acc[r][1] = fmaf(a, bv.y, acc[r][1]);
                acc[r][2] = fmaf(a, bv.z, acc[r][2]);
                acc[r][3] = fmaf(a, bv.w, acc[r][3]);
            }
        }
        __syncthreads();
    }

    // epilogue: z = acc + T[batch[row]], partial = sum_j sigmoid(z_j)*w3_j
    float w3v[4];
#pragma unroll
    for (int j = 0; j < 4; j++) w3v[j] = w3[c0 + j];

    float* p_s = W_s;   // 32 rows x 65 (padded) partials; 8.3 KB << 32 KB
#pragma unroll
    for (int r = 0; r < 8; r++) {
        int row = row0 + ty * 8 + r;
        int seg = batch[row];
        const float* Trow = T + (size_t)seg * DIM;
        float part = 0.f;
#pragma unroll
        for (int j = 0; j < 4; j++) {
            float z = acc[r][j] + Trow[c0 + j];
            float s = 1.f / (1.f + __expf(-z));
            part = fmaf(s, w3v[j], part);
        }
        p_s[(ty * 8 + r) * 65 + tx] = part;
    }
    __syncthreads();
    if (tid < 32) {
        float s = 0.f;
#pragma unroll
        for (int j = 0; j < 64; j++) s += p_s[tid * 65 + j];
        att[row0 + tid] = s;
    }
}

// ---------------------------------------------------------------------------
extern "C" void kernel_launch(void* const* d_in, const int* in_sizes, int n_in,
                              void* d_out, int out_size)
{
    const float* x     = (const float*)d_in[0];
    const int*   batch = (const int*)d_in[1];
    const float* mask  = (const float*)d_in[2];

    // num_segments may appear as a scalar input at slot 3; detect by size.
    int o = (in_sizes[3] == 1) ? 4 : 3;
    const float* W1 = (const float*)d_in[o + 0];
    const float* b1 = (const float*)d_in[o + 1];
    const float* W2 = (const float*)d_in[o + 2];
    const float* b2 = (const float*)d_in[o + 3];
    const float* w3 = (const float*)d_in[o + 4];
    const float* W4 = (const float*)d_in[o + 5];
    const float* b4 = (const float*)d_in[o + 6];

    float *lr, *T, *gr, *att;
    int* ss;
    cudaGetSymbolAddress((void**)&lr,  g_localrep);
    cudaGetSymbolAddress((void**)&T,   g_T);
    cudaGetSymbolAddress((void**)&gr,  g_globalrep);
    cudaGetSymbolAddress((void**)&att, g_att);
    cudaGetSymbolAddress((void**)&ss,  g_segstart);

    // K0: segment offsets (16385 binary searches)
    segstart_kernel<<<(BSEG + 256) / 256, 256>>>(batch, ss);
    // K1: local_rep = segment_sum(x * mask)
    seg_pool_kernel<<<BSEG, 64>>>(x, mask, ss, lr);
    // K2: T = local_rep @ W1 + b1 + b2
    gemm_kernel<<<BSEG / MT, 256>>>(lr, nullptr, W1, DIM, b1, b2, T);
    // K3: att = sigmoid(x @ W2 + T[batch]) . w3
    att_kernel<<<NROWS / MT, 256>>>(x, W2, T, batch, w3, att);
    // K4: global_rep = segment_sum(x * att)
    seg_pool_kernel<<<BSEG, 64>>>(x, att, ss, gr);
    // K5: out = [local_rep | global_rep] @ W4 + b4
    gemm_kernel<<<BSEG / MT, 256>>>(lr, gr, W4, 2 * DIM, b4, nullptr, (float*)d_out);
}

// round 17
// speedup vs baseline: 1.0922x; 1.0922x over previous
#include <cuda_runtime.h>
#include <math.h>

#define NROWS 500000
#define DIM   256
#define BSEG  16384
#define KC    32
#define MT    32

typedef unsigned long long u64;

__device__ __forceinline__ u64 ffma2(u64 a, u64 b, u64 c) {
    u64 d;
    asm("fma.rn.f32x2 %0, %1, %2, %3;" : "=l"(d) : "l"(a), "l"(b), "l"(c));
    return d;
}

union F2U { u64 u; float2 f; };

// ---- scratch (device globals: no cudaMalloc allowed) ----
__device__ float g_localrep[BSEG * DIM];
__device__ float g_T[BSEG * DIM];
__device__ float g_globalrep[BSEG * DIM];
__device__ float g_att[NROWS];
__device__ int   g_segstart[BSEG + 1];

// ---------------------------------------------------------------------------
// K0: segment offsets via binary search (batch is sorted).
// ---------------------------------------------------------------------------
__global__ void segstart_kernel(const int* __restrict__ batch, int* __restrict__ segstart)
{
    int t = blockIdx.x * blockDim.x + threadIdx.x;
    if (t > BSEG) return;
    int lo = 0, hi = NROWS;
    while (lo < hi) {
        int m = (lo + hi) >> 1;
        if (batch[m] < t) lo = m + 1; else hi = m;
    }
    segstart[t] = lo;
}

// ---------------------------------------------------------------------------
// K1 / K4: per-segment weighted sum: out[b,:] = sum_{i in seg b} w[i] * x[i,:]
// ---------------------------------------------------------------------------
__global__ __launch_bounds__(64) void seg_pool_kernel(
    const float* __restrict__ x, const float* __restrict__ w,
    const int* __restrict__ segstart, float* __restrict__ out)
{
    int b = blockIdx.x;
    int s = segstart[b], e = segstart[b + 1];
    int c = threadIdx.x * 4;

    float4 a0 = make_float4(0.f, 0.f, 0.f, 0.f);
    float4 a1 = make_float4(0.f, 0.f, 0.f, 0.f);

    int i = s;
    for (; i + 1 < e; i += 2) {
        float w0 = w[i], w1 = w[i + 1];
        float4 v0 = *(const float4*)&x[(size_t)i * DIM + c];
        float4 v1 = *(const float4*)&x[(size_t)(i + 1) * DIM + c];
        a0.x = fmaf(w0, v0.x, a0.x); a0.y = fmaf(w0, v0.y, a0.y);
        a0.z = fmaf(w0, v0.z, a0.z); a0.w = fmaf(w0, v0.w, a0.w);
        a1.x = fmaf(w1, v1.x, a1.x); a1.y = fmaf(w1, v1.y, a1.y);
        a1.z = fmaf(w1, v1.z, a1.z); a1.w = fmaf(w1, v1.w, a1.w);
    }
    if (i < e) {
        float w0 = w[i];
        float4 v0 = *(const float4*)&x[(size_t)i * DIM + c];
        a0.x = fmaf(w0, v0.x, a0.x); a0.y = fmaf(w0, v0.y, a0.y);
        a0.z = fmaf(w0, v0.z, a0.z); a0.w = fmaf(w0, v0.w, a0.w);
    }
    a0.x += a1.x; a0.y += a1.y; a0.z += a1.z; a0.w += a1.w;
    *(float4*)&out[(size_t)b * DIM + c] = a0;
}

// ---------------------------------------------------------------------------
// Shared mainloop macro pieces for the FFMA2 GEMM tiling:
//   block = 128 threads, tile = 32 rows x 256 cols
//   thread (tx = tid&31, ty = tid>>5) owns 8 rows (ty*8..+7) and 8 cols
//   (tx*4..+3 and 128+tx*4..+3).  A staged duplicated as {a,a} float2 pairs.
// ---------------------------------------------------------------------------

// stage A chunk (32 rows x 32 k) duplicated into A_s [row*64 + k*2]
__device__ __forceinline__ void stage_A_dup(
    float* A_s, const float* __restrict__ A, int row0, int acol, int tid)
{
    int arow = tid >> 2;
    int kbase = (tid & 3) * 8;
    const float* src = &A[(size_t)(row0 + arow) * DIM + acol + kbase];
    float4 v0 = *(const float4*)&src[0];
    float4 v1 = *(const float4*)&src[4];
    float* dst = &A_s[arow * 64 + kbase * 2];
    *(float4*)&dst[0]  = make_float4(v0.x, v0.x, v0.y, v0.y);
    *(float4*)&dst[4]  = make_float4(v0.z, v0.z, v0.w, v0.w);
    *(float4*)&dst[8]  = make_float4(v1.x, v1.x, v1.y, v1.y);
    *(float4*)&dst[12] = make_float4(v1.z, v1.z, v1.w, v1.w);
}

// stage W chunk (32 k x 256 cols)
__device__ __forceinline__ void stage_W(
    float* W_s, const float* __restrict__ W, int kb, int tid)
{
#pragma unroll
    for (int j = 0; j < 16; j++) {
        int idx  = tid + j * 128;
        int krow = idx >> 6;
        int c4   = (idx & 63) << 2;
        *(float4*)&W_s[krow * DIM + c4] =
            *(const float4*)&W[(size_t)(kb + krow) * DIM + c4];
    }
}

// mainloop over one 32-k chunk: acc[8][4] f32x2 accumulators
__device__ __forceinline__ void mainloop_chunk(
    const float* A_s, const float* W_s, int ty, int c0, u64 acc[8][4])
{
#pragma unroll
    for (int kk = 0; kk < KC; kk += 2) {
        ulonglong2 w00 = *(const ulonglong2*)&W_s[kk * DIM + c0];
        ulonglong2 w01 = *(const ulonglong2*)&W_s[kk * DIM + c0 + 128];
        ulonglong2 w10 = *(const ulonglong2*)&W_s[(kk + 1) * DIM + c0];
        ulonglong2 w11 = *(const ulonglong2*)&W_s[(kk + 1) * DIM + c0 + 128];
#pragma unroll
        for (int r = 0; r < 8; r++) {
            ulonglong2 a = *(const ulonglong2*)&A_s[(ty * 8 + r) * 64 + kk * 2];
            acc[r][0] = ffma2(a.x, w00.x, acc[r][0]);
            acc[r][1] = ffma2(a.x, w00.y, acc[r][1]);
            acc[r][2] = ffma2(a.x, w01.x, acc[r][2]);
            acc[r][3] = ffma2(a.x, w01.y, acc[r][3]);
            acc[r][0] = ffma2(a.y, w10.x, acc[r][0]);
            acc[r][1] = ffma2(a.y, w10.y, acc[r][1]);
            acc[r][2] = ffma2(a.y, w11.x, acc[r][2]);
            acc[r][3] = ffma2(a.y, w11.y, acc[r][3]);
        }
    }
}

// ---------------------------------------------------------------------------
// K2 / K5: C[M,256] = A@W + bias0 (+bias1).  K = 256 or 512 (A0|A1 concat).
// ---------------------------------------------------------------------------
__global__ __launch_bounds__(128, 4) void gemm_kernel(
    const float* __restrict__ A0, const float* __restrict__ A1,
    const float* __restrict__ W, int K,
    const float* __restrict__ bias0, const float* __restrict__ bias1,
    float* __restrict__ C)
{
    __shared__ float W_s[KC * DIM];   // 32 KB
    __shared__ float A_s[MT * 64];    // 8 KB (duplicated pairs)

    const int tid = threadIdx.x;
    const int tx  = tid & 31;
    const int ty  = tid >> 5;
    const int row0 = blockIdx.x * MT;
    const int c0   = tx * 4;

    u64 acc[8][4];
#pragma unroll
    for (int r = 0; r < 8; r++)
#pragma unroll
        for (int j = 0; j < 4; j++) acc[r][j] = 0ull;

    for (int kb = 0; kb < K; kb += KC) {
        const float* A = (kb < DIM) ? A0 : A1;
        stage_A_dup(A_s, A, row0, kb & (DIM - 1), tid);
        stage_W(W_s, W, kb, tid);
        __syncthreads();
        mainloop_chunk(A_s, W_s, ty, c0, acc);
        __syncthreads();
    }

    float4 bl = *(const float4*)&bias0[c0];
    float4 bh = *(const float4*)&bias0[c0 + 128];
    if (bias1) {
        float4 cl = *(const float4*)&bias1[c0];
        float4 ch = *(const float4*)&bias1[c0 + 128];
        bl.x += cl.x; bl.y += cl.y; bl.z += cl.z; bl.w += cl.w;
        bh.x += ch.x; bh.y += ch.y; bh.z += ch.z; bh.w += ch.w;
    }
#pragma unroll
    for (int r = 0; r < 8; r++) {
        int row = row0 + ty * 8 + r;
        F2U u0, u1, u2, u3;
        u0.u = acc[r][0]; u1.u = acc[r][1]; u2.u = acc[r][2]; u3.u = acc[r][3];
        float4 o0 = make_float4(u0.f.x + bl.x, u0.f.y + bl.y,
                                u1.f.x + bl.z, u1.f.y + bl.w);
        float4 o1 = make_float4(u2.f.x + bh.x, u2.f.y + bh.y,
                                u3.f.x + bh.z, u3.f.y + bh.w);
        *(float4*)&C[(size_t)row * DIM + c0]       = o0;
        *(float4*)&C[(size_t)row * DIM + c0 + 128] = o1;
    }
}

// ---------------------------------------------------------------------------
// K3: att[i] = sigmoid(x[i]@W2 + T[batch[i]]) . w3   (32.8 G-FMA, FFMA2)
// N = 500000 = 32 * 15625 exactly -> no row guards.
// ---------------------------------------------------------------------------
__global__ __launch_bounds__(128, 4) void att_kernel(
    const float* __restrict__ x, const float* __restrict__ W2,
    const float* __restrict__ T, const int* __restrict__ batch,
    const float* __restrict__ w3, float* __restrict__ att)
{
    __shared__ float W_s[KC * DIM];
    __shared__ float A_s[MT * 64];

    const int tid = threadIdx.x;
    const int tx  = tid & 31;
    const int ty  = tid >> 5;
    const int row0 = blockIdx.x * MT;
    const int c0   = tx * 4;

    u64 acc[8][4];
#pragma unroll
    for (int r = 0; r < 8; r++)
#pragma unroll
        for (int j = 0; j < 4; j++) acc[r][j] = 0ull;

    for (int kb = 0; kb < DIM; kb += KC) {
        stage_A_dup(A_s, x, row0, kb, tid);
        stage_W(W_s, W2, kb, tid);
        __syncthreads();
        mainloop_chunk(A_s, W_s, ty, c0, acc);
        __syncthreads();
    }

    // epilogue: z = acc + T[batch[row]]; part = sum_cols sigmoid(z)*w3
    float4 wl = *(const float4*)&w3[c0];
    float4 wh = *(const float4*)&w3[c0 + 128];

#pragma unroll
    for (int r = 0; r < 8; r++) {
        int row = row0 + ty * 8 + r;
        int seg = batch[row];           // uniform across warp (same row)
        const float* Trow = T + (size_t)seg * DIM;
        float4 t0 = *(const float4*)&Trow[c0];
        float4 t1 = *(const float4*)&Trow[c0 + 128];

        F2U u0, u1, u2, u3;
        u0.u = acc[r][0]; u1.u = acc[r][1]; u2.u = acc[r][2]; u3.u = acc[r][3];

        float part = 0.f;
        {
            float z, s;
            z = u0.f.x + t0.x; s = 1.f / (1.f + __expf(-z)); part = fmaf(s, wl.x, part);
            z = u0.f.y + t0.y; s = 1.f / (1.f + __expf(-z)); part = fmaf(s, wl.y, part);
            z = u1.f.x + t0.z; s = 1.f / (1.f + __expf(-z)); part = fmaf(s, wl.z, part);
            z = u1.f.y + t0.w; s = 1.f / (1.f + __expf(-z)); part = fmaf(s, wl.w, part);
            z = u2.f.x + t1.x; s = 1.f / (1.f + __expf(-z)); part = fmaf(s, wh.x, part);
            z = u2.f.y + t1.y; s = 1.f / (1.f + __expf(-z)); part = fmaf(s, wh.y, part);
            z = u3.f.x + t1.z; s = 1.f / (1.f + __expf(-z)); part = fmaf(s, wh.z, part);
            z = u3.f.y + t1.w; s = 1.f / (1.f + __expf(-z)); part = fmaf(s, wh.w, part);
        }
        // warp reduce: all 32 lanes of this warp hold partials for the SAME row
#pragma unroll
        for (int off = 16; off > 0; off >>= 1)
            part += __shfl_xor_sync(0xFFFFFFFFu, part, off);
        if (tx == r) att[row] = part;
    }
}

// ---------------------------------------------------------------------------
extern "C" void kernel_launch(void* const* d_in, const int* in_sizes, int n_in,
                              void* d_out, int out_size)
{
    const float* x     = (const float*)d_in[0];
    const int*   batch = (const int*)d_in[1];
    const float* mask  = (const float*)d_in[2];

    int o = (in_sizes[3] == 1) ? 4 : 3;   // skip scalar num_segments if present
    const float* W1 = (const float*)d_in[o + 0];
    const float* b1 = (const float*)d_in[o + 1];
    const float* W2 = (const float*)d_in[o + 2];
    const float* b2 = (const float*)d_in[o + 3];
    const float* w3 = (const float*)d_in[o + 4];
    const float* W4 = (const float*)d_in[o + 5];
    const float* b4 = (const float*)d_in[o + 6];

    float *lr, *T, *gr, *att;
    int* ss;
    cudaGetSymbolAddress((void**)&lr,  g_localrep);
    cudaGetSymbolAddress((void**)&T,   g_T);
    cudaGetSymbolAddress((void**)&gr,  g_globalrep);
    cudaGetSymbolAddress((void**)&att, g_att);
    cudaGetSymbolAddress((void**)&ss,  g_segstart);

    segstart_kernel<<<(BSEG + 256) / 256, 256>>>(batch, ss);
    seg_pool_kernel<<<BSEG, 64>>>(x, mask, ss, lr);
    gemm_kernel<<<BSEG / MT, 128>>>(lr, nullptr, W1, DIM, b1, b2, T);
    att_kernel<<<NROWS / MT, 128>>>(x, W2, T, batch, w3, att);
    seg_pool_kernel<<<BSEG, 64>>>(x, att, ss, gr);
    gemm_kernel<<<BSEG / MT, 128>>>(lr, gr, W4, 2 * DIM, b4, nullptr, (float*)d_out);
}